// round 16
// baseline (speedup 1.0000x reference)
#include <cuda_runtime.h>

#define NDIR   64
#define NBIN   65
#define INV_DH 0.28867513459481287f    // 1/(2*sqrt(3))
#define D_PER  4
#define NGRP   (NDIR / D_PER)          // 16
#define TPB    128
#define NTILE  32
#define ISEG   4
#define ILEN   16
#define NSLOT  (NTILE * ISEG)          // 128 partials per direction
#define SBIN   65
#define NX     262144
#define XPAD   4224
#define NXP    (NX + XPAD)
#define BIGM   1.0e30f
#define PADV4  ((NXP + 3) / 4)
#define PADBLK ((PADV4 + 255) / 256)   // pad blocks (256 thr each)

__device__ float g_part[NDIR * NSLOT * SBIN];
__device__ float g_xp[NXP];

// Per-direction constants: {cA, cB, cC} per dir.
// cA = {B1,B2,B3,B4}; cB = {B5,B6,B7,sgn}; cC = {A1,A2,A0,stepF}
__device__   float4 g_dconst[NDIR * 3];
__constant__ float4 c_dir[NDIR * 3];

// Fused pad + per-direction constant prep. Blocks [0, PADBLK) pad x into
// g_xp; block PADBLK computes the 64 direction constant triples.
__global__ void prep_pad_kernel(const float* __restrict__ x,
                                const float* __restrict__ dirs) {
    if (blockIdx.x < PADBLK) {
        int t = blockIdx.x * 256 + threadIdx.x;  // float4 index
        if (t < PADV4 && t * 4 < NXP) {
            float4 v;
            if (t * 4 + 3 < NX) {
                v = reinterpret_cast<const float4*>(x)[t];
            } else {
                v.x = (t*4+0 < NX) ? x[t*4+0] : 0.f;
                v.y = (t*4+1 < NX) ? x[t*4+1] : 0.f;
                v.z = (t*4+2 < NX) ? x[t*4+2] : 0.f;
                v.w = (t*4+3 < NX) ? x[t*4+3] : 0.f;
            }
            reinterpret_cast<float4*>(g_xp)[t] = v;
        }
        return;
    }
    int k = threadIdx.x;
    if (k >= NDIR) return;
    float d0 = dirs[3*k], d1 = dirs[3*k+1], d2 = dirs[3*k+2];
    float p0 = fmaxf(d0, 0.f), p1 = fmaxf(d1, 0.f), p2 = fmaxf(d2, 0.f);
    float q1 = p0*INV_DH, q2 = p1*INV_DH, q3 = p2*INV_DH;
    float q4 = (p1+p2)*INV_DH, q5 = (p0+p2)*INV_DH;
    float q6 = (p0+p1)*INV_DH, q7 = (p0+p1+p2)*INV_DH;
    float d0I = d0*INV_DH, d1I = d1*INV_DH, d2I = d2*INV_DH;
    float4 A, B, C;
    if (d0 >= 0.f) {
        // pos: F = f+1, slot t=ceil(f)=b; accLO->bin t, accHI->t+1.
        A = make_float4((q1-1.f)*BIGM, (q2-1.f)*BIGM, (q3-1.f)*BIGM, (q4-1.f)*BIGM);
        B = make_float4((q5-1.f)*BIGM, (q6-1.f)*BIGM, (q7-1.f)*BIGM,  BIGM);
        C = make_float4(d1I, d2I, 33.0f, d0I);
    } else {
        // neg: F = 64-f, slot t=64-b; slot u <-> bin 65-u; accLO=S1.
        A = make_float4(q1*BIGM, q2*BIGM, q3*BIGM, q4*BIGM);
        B = make_float4(q5*BIGM, q6*BIGM, q7*BIGM, -BIGM);
        C = make_float4(-d1I, -d2I, 32.0f, -d0I);
    }
    g_dconst[3*k+0] = A;
    g_dconst[3*k+1] = B;
    g_dconst[3*k+2] = C;
}

__device__ __forceinline__ float satfma(float a, float b, float c) {
    float r;
    asm("fma.rn.sat.f32 %0, %1, %2, %3;" : "=f"(r) : "f"(a), "f"(b), "f"(c));
    return r;
}
// Keep "memory" clobber: empirically load-bearing (R8). Const-space reads are
// immutable from device code and remain hoistable across it.
#define RED_IF_NE(addr, v, tt, pp) \
    asm volatile("{ .reg .pred p; setp.ne.s32 p, %2, %3;\n\t" \
                 "@p red.shared.add.f32 [%0], %1; }" \
                 :: "r"(addr), "f"(v), "r"(tt), "r"(pp) : "memory")

__device__ __forceinline__ void red_sh(unsigned addr, float v) {
    asm volatile("red.shared.add.f32 [%0], %1;" :: "r"(addr), "f"(v) : "memory");
}

__global__ void __launch_bounds__(TPB, 9) main_kernel() {
    const int g   = blockIdx.z;
    const int seg = blockIdx.y;
    const int tid = threadIdx.x;
    __shared__ float sh[D_PER][68];       // histogram slots, padded rows (272B)

    for (int t = tid; t < D_PER * 68; t += TPB) ((float*)sh)[t] = 0.f;
    __syncthreads();

    const int base = blockIdx.x * TPB + tid;     // (j,l) column
    const int j = base >> 6, l = base & 63;
    const float mj = (j < 63) ? 1.f : 0.f;
    const float ml = (l < 63) ? 1.f : 0.f;
    const float mjl = mj * ml;
    const float jf = (float)j, lf = (float)l;
    const int i0 = seg * ILEN;
    const int kb = g * D_PER;                    // first direction of this group

    float baseF[D_PER], stepF[D_PER], accLO[D_PER], accHI[D_PER];
    int prevb[D_PER];
    const unsigned row0 = (unsigned)__cvta_generic_to_shared(&sh[0][0]);
    #pragma unroll
    for (int d = 0; d < D_PER; d++) {
        float4 c = c_dir[3*(kb+d)+2];
        baseF[d] = fmaf(c.w, (float)i0, fmaf(c.x, jf, fmaf(c.y, lf, c.z)));
        stepF[d] = c.w;
        prevb[d] = (int)floorf(baseF[d]);
        accLO[d] = 0.f; accHI[d] = 0.f;
    }

    int idx = i0 * 4096 + base;
    float c00 = g_xp[idx];
    float c01 = g_xp[idx + 1];
    float c10 = g_xp[idx + 64];
    float c11 = g_xp[idx + 65];

    #pragma unroll 4
    for (int ii = 0; ii < ILEN; ii++) {
        const float mi = ((i0 + ii) < 63) ? 1.f : 0.f;
        const int nidx = idx + 4096;
        float n00 = g_xp[nidx];
        float n01 = g_xp[nidx + 1];
        float n10 = g_xp[nidx + 64];
        float n11 = g_xp[nidx + 65];

        float m_i   = fmaxf(c00, n00);
        float mc    = fmaxf(fmaxf(c00, c01), fmaxf(c10, c11));
        float v_ei  = -m_i * mi;
        float v_ej  = -fmaxf(c00, c10) * mj;
        float v_el  = -fmaxf(c00, c01) * ml;
        float v_fjl = mc * mjl;
        float v_fil = fmaxf(m_i, fmaxf(c01, n01)) * (mi * ml);
        float v_fij = fmaxf(m_i, fmaxf(c10, n10)) * (mi * mj);
        float v_c   = -fmaxf(mc, fmaxf(fmaxf(n00, n01), fmaxf(n10, n11))) * (mi * mjl);
        float T = ((c00 + v_ei) + (v_ej + v_el)) + ((v_fjl + v_fil) + (v_fij + v_c));
        float fi = (float)ii;

        #pragma unroll
        for (int d = 0; d < D_PER; d++) {
            float F  = fmaf(stepF[d], fi, baseF[d]);
            float tf = floorf(F);
            int   t  = (int)tf;
            float fr = F - tf;

            float4 a4 = c_dir[3*(kb+d)];      // constant bank — no L1tex,
            float4 b4 = c_dir[3*(kb+d)+1];    //  hoistable across clobbers
            float m1 = satfma(b4.w, fr, a4.x);
            float m2 = satfma(b4.w, fr, a4.y);
            float m3 = satfma(b4.w, fr, a4.z);
            float m4 = satfma(b4.w, fr, a4.w);
            float m5 = satfma(b4.w, fr, b4.x);
            float m6 = satfma(b4.w, fr, b4.y);
            float m7 = satfma(b4.w, fr, b4.z);

            float Sa = fmaf(m1, v_ei, fmaf(m3, v_el, fmaf(m5, v_fil, m7 * v_c)));
            float Sb = fmaf(m2, v_ej, fmaf(m4, v_fjl, m6 * v_fij));
            float S1 = Sa + Sb;
            float S0 = T - S1;
            float cLO = (b4.w > 0.f) ? S0 : S1;   // pos: S0, neg: S1
            float cHI = T - cLO;

            RED_IF_NE(row0 + (unsigned)(d * 272) + ((unsigned)prevb[d] << 2),
                      accLO[d], t, prevb[d]);
            bool adv = (t != prevb[d]);
            float nLO = adv ? accHI[d] : accLO[d];
            float nHI = adv ? 0.f : accHI[d];
            accLO[d] = nLO + cLO;
            accHI[d] = nHI + cHI;
            prevb[d] = t;
        }

        c00 = n00; c01 = n01; c10 = n10; c11 = n11;
        idx = nidx;
    }

    #pragma unroll
    for (int d = 0; d < D_PER; d++) {
        red_sh(row0 + (unsigned)(d * 272) + ((unsigned)prevb[d] << 2),       accLO[d]);
        red_sh(row0 + (unsigned)(d * 272) + ((unsigned)(prevb[d] + 1) << 2), accHI[d]);
    }
    __syncthreads();

    const int slot = blockIdx.x * ISEG + seg;
    for (int t = tid; t < D_PER * SBIN; t += TPB) {
        int d = t / SBIN, bin = t - d * SBIN;
        int k = kb + d;
        bool rev = (c_dir[3*k+1].w < 0.f);       // sign of sgn (const bank)
        int u = rev ? (65 - bin) : bin;
        g_part[(k * NSLOT + slot) * SBIN + bin] = sh[d][u];
    }
}

// One block per direction; 8 groups of 65 threads reduce 16 slots each.
__global__ void __launch_bounds__(520) finalize(float* __restrict__ out) {
    const int k   = blockIdx.x;
    const int tid = threadIdx.x;
    const int sub = tid / NBIN;
    const int bin = tid - sub * NBIN;
    __shared__ float red[8][NBIN];

    float acc = 0.f;
    const float* p = &g_part[k * NSLOT * SBIN + bin];
    #pragma unroll
    for (int s = 0; s < NSLOT / 8; s++)
        acc += p[(sub * (NSLOT / 8) + s) * SBIN];
    red[sub][bin] = acc;
    __syncthreads();

    if (sub == 0) {
        float t = 0.f;
        #pragma unroll
        for (int r = 0; r < 8; r++) t += red[r][bin];
        red[0][bin] = t;
    }
    __syncthreads();
    if (sub == 0) {
        float a = 0.f;
        for (int b = 0; b <= bin; b++) a += red[0][b];
        out[k * NBIN + bin] = a;
    }
}

extern "C" void kernel_launch(void* const* d_in, const int* in_sizes, int n_in,
                              void* d_out, int out_size) {
    const float* x    = (const float*)d_in[0];
    const float* dirs = (const float*)d_in[1];
    float* out = (float*)d_out;

    prep_pad_kernel<<<PADBLK + 1, 256>>>(x, dirs);

    void* src = nullptr;
    cudaGetSymbolAddress(&src, g_dconst);                   // pure query, capture-safe
    cudaMemcpyToSymbolAsync(c_dir, src, sizeof(float4) * NDIR * 3,
                            0, cudaMemcpyDeviceToDevice, 0);

    main_kernel<<<dim3(NTILE, ISEG, NGRP), TPB>>>();
    finalize<<<NDIR, 520>>>(out);
}

// round 17
// speedup vs baseline: 1.0983x; 1.0983x over previous
#include <cuda_runtime.h>

#define NDIR   64
#define NBIN   65
#define INV_DH 0.28867513459481287f    // 1/(2*sqrt(3))
#define D_PER  4
#define NGRP   (NDIR / D_PER)          // 16
#define TPB    128
#define NTILE  32
#define ISEG   4
#define ILEN   16
#define NSLOT  (NTILE * ISEG)          // 128 partials per direction
#define SBIN   65
#define NX     262144
#define BIGM   1.0e30f

__device__ float g_part[NDIR * NSLOT * SBIN];

// Per-direction constants: {cA, cB, cC} per dir.
// cA = {B1,B2,B3,B4}; cB = {B5,B6,B7,sgn}; cC = {A1,A2,A0,stepF}
__device__   float4 g_dconst[NDIR * 3];
__constant__ float4 c_dir[NDIR * 3];

// Per-direction constant prep, split in two launches (capture-slot shaping).
__global__ void prep_kernel(const float* __restrict__ dirs, int k0) {
    int k = k0 + threadIdx.x;
    if (k >= NDIR) return;
    float d0 = dirs[3*k], d1 = dirs[3*k+1], d2 = dirs[3*k+2];
    float p0 = fmaxf(d0, 0.f), p1 = fmaxf(d1, 0.f), p2 = fmaxf(d2, 0.f);
    float q1 = p0*INV_DH, q2 = p1*INV_DH, q3 = p2*INV_DH;
    float q4 = (p1+p2)*INV_DH, q5 = (p0+p2)*INV_DH;
    float q6 = (p0+p1)*INV_DH, q7 = (p0+p1+p2)*INV_DH;
    float d0I = d0*INV_DH, d1I = d1*INV_DH, d2I = d2*INV_DH;
    float4 A, B, C;
    if (d0 >= 0.f) {
        // pos: F = f+1, slot t=ceil(f)=b; accLO->bin t, accHI->t+1.
        A = make_float4((q1-1.f)*BIGM, (q2-1.f)*BIGM, (q3-1.f)*BIGM, (q4-1.f)*BIGM);
        B = make_float4((q5-1.f)*BIGM, (q6-1.f)*BIGM, (q7-1.f)*BIGM,  BIGM);
        C = make_float4(d1I, d2I, 33.0f, d0I);
    } else {
        // neg: F = 64-f, slot t=64-b; slot u <-> bin 65-u; accLO=S1.
        A = make_float4(q1*BIGM, q2*BIGM, q3*BIGM, q4*BIGM);
        B = make_float4(q5*BIGM, q6*BIGM, q7*BIGM, -BIGM);
        C = make_float4(-d1I, -d2I, 32.0f, -d0I);
    }
    g_dconst[3*k+0] = A;
    g_dconst[3*k+1] = B;
    g_dconst[3*k+2] = C;
}

__device__ __forceinline__ float satfma(float a, float b, float c) {
    float r;
    asm("fma.rn.sat.f32 %0, %1, %2, %3;" : "=f"(r) : "f"(a), "f"(b), "f"(c));
    return r;
}
// Keep "memory" clobber: empirically load-bearing (R8). Const-space reads are
// immutable from device code and remain hoistable across it.
#define RED_IF_NE(addr, v, tt, pp) \
    asm volatile("{ .reg .pred p; setp.ne.s32 p, %2, %3;\n\t" \
                 "@p red.shared.add.f32 [%0], %1; }" \
                 :: "r"(addr), "f"(v), "r"(tt), "r"(pp) : "memory")

__device__ __forceinline__ void red_sh(unsigned addr, float v) {
    asm volatile("red.shared.add.f32 [%0], %1;" :: "r"(addr), "f"(v) : "memory");
}

// Reads x directly (no padded copy). n-plane loads are index-clamped to
// NX-1; every clamp-affected value is provably multiplied by a zero mask
// (i=63 -> mi, j=63 -> mj, l=63 -> ml), so results are exact.
__global__ void __launch_bounds__(TPB, 9) main_kernel(const float* __restrict__ x) {
    const int g   = blockIdx.z;
    const int seg = blockIdx.y;
    const int tid = threadIdx.x;
    __shared__ float sh[D_PER][68];       // histogram slots, padded rows (272B)

    for (int t = tid; t < D_PER * 68; t += TPB) ((float*)sh)[t] = 0.f;
    __syncthreads();

    const int base = blockIdx.x * TPB + tid;     // (j,l) column
    const int j = base >> 6, l = base & 63;
    const float mj = (j < 63) ? 1.f : 0.f;
    const float ml = (l < 63) ? 1.f : 0.f;
    const float mjl = mj * ml;
    const float jf = (float)j, lf = (float)l;
    const int i0 = seg * ILEN;
    const int kb = g * D_PER;                    // first direction of this group

    float baseF[D_PER], stepF[D_PER], accLO[D_PER], accHI[D_PER];
    int prevb[D_PER];
    const unsigned row0 = (unsigned)__cvta_generic_to_shared(&sh[0][0]);
    #pragma unroll
    for (int d = 0; d < D_PER; d++) {
        float4 c = c_dir[3*(kb+d)+2];
        baseF[d] = fmaf(c.w, (float)i0, fmaf(c.x, jf, fmaf(c.y, lf, c.z)));
        stepF[d] = c.w;
        prevb[d] = (int)floorf(baseF[d]);
        accLO[d] = 0.f; accHI[d] = 0.f;
    }

    // Prologue c-plane loads: i0 <= 48, so idx+65 <= 48*4096+4095+65 < NX. Safe.
    int idx = i0 * 4096 + base;
    float c00 = x[idx];
    float c01 = x[idx + 1];
    float c10 = x[idx + 64];
    float c11 = x[idx + 65];

    #pragma unroll 4
    for (int ii = 0; ii < ILEN; ii++) {
        const float mi = ((i0 + ii) < 63) ? 1.f : 0.f;
        const int nidx = idx + 4096;
        float n00 = x[min(nidx,      NX - 1)];
        float n01 = x[min(nidx + 1,  NX - 1)];
        float n10 = x[min(nidx + 64, NX - 1)];
        float n11 = x[min(nidx + 65, NX - 1)];

        float m_i   = fmaxf(c00, n00);
        float mc    = fmaxf(fmaxf(c00, c01), fmaxf(c10, c11));
        float v_ei  = -m_i * mi;
        float v_ej  = -fmaxf(c00, c10) * mj;
        float v_el  = -fmaxf(c00, c01) * ml;
        float v_fjl = mc * mjl;
        float v_fil = fmaxf(m_i, fmaxf(c01, n01)) * (mi * ml);
        float v_fij = fmaxf(m_i, fmaxf(c10, n10)) * (mi * mj);
        float v_c   = -fmaxf(mc, fmaxf(fmaxf(n00, n01), fmaxf(n10, n11))) * (mi * mjl);
        float T = ((c00 + v_ei) + (v_ej + v_el)) + ((v_fjl + v_fil) + (v_fij + v_c));
        float fi = (float)ii;

        #pragma unroll
        for (int d = 0; d < D_PER; d++) {
            float F  = fmaf(stepF[d], fi, baseF[d]);
            float tf = floorf(F);
            int   t  = (int)tf;
            float fr = F - tf;

            float4 a4 = c_dir[3*(kb+d)];      // constant bank — no L1tex,
            float4 b4 = c_dir[3*(kb+d)+1];    //  hoistable across clobbers
            float m1 = satfma(b4.w, fr, a4.x);
            float m2 = satfma(b4.w, fr, a4.y);
            float m3 = satfma(b4.w, fr, a4.z);
            float m4 = satfma(b4.w, fr, a4.w);
            float m5 = satfma(b4.w, fr, b4.x);
            float m6 = satfma(b4.w, fr, b4.y);
            float m7 = satfma(b4.w, fr, b4.z);

            float Sa = fmaf(m1, v_ei, fmaf(m3, v_el, fmaf(m5, v_fil, m7 * v_c)));
            float Sb = fmaf(m2, v_ej, fmaf(m4, v_fjl, m6 * v_fij));
            float S1 = Sa + Sb;
            float S0 = T - S1;
            float cLO = (b4.w > 0.f) ? S0 : S1;   // pos: S0, neg: S1
            float cHI = T - cLO;

            RED_IF_NE(row0 + (unsigned)(d * 272) + ((unsigned)prevb[d] << 2),
                      accLO[d], t, prevb[d]);
            bool adv = (t != prevb[d]);
            float nLO = adv ? accHI[d] : accLO[d];
            float nHI = adv ? 0.f : accHI[d];
            accLO[d] = nLO + cLO;
            accHI[d] = nHI + cHI;
            prevb[d] = t;
        }

        c00 = n00; c01 = n01; c10 = n10; c11 = n11;
        idx = nidx;
    }

    #pragma unroll
    for (int d = 0; d < D_PER; d++) {
        red_sh(row0 + (unsigned)(d * 272) + ((unsigned)prevb[d] << 2),       accLO[d]);
        red_sh(row0 + (unsigned)(d * 272) + ((unsigned)(prevb[d] + 1) << 2), accHI[d]);
    }
    __syncthreads();

    const int slot = blockIdx.x * ISEG + seg;
    for (int t = tid; t < D_PER * SBIN; t += TPB) {
        int d = t / SBIN, bin = t - d * SBIN;
        int k = kb + d;
        bool rev = (c_dir[3*k+1].w < 0.f);       // sign of sgn (const bank)
        int u = rev ? (65 - bin) : bin;
        g_part[(k * NSLOT + slot) * SBIN + bin] = sh[d][u];
    }
}

// One block per direction; 8 groups of 65 threads reduce 16 slots each.
__global__ void __launch_bounds__(520) finalize(float* __restrict__ out) {
    const int k   = blockIdx.x;
    const int tid = threadIdx.x;
    const int sub = tid / NBIN;
    const int bin = tid - sub * NBIN;
    __shared__ float red[8][NBIN];

    float acc = 0.f;
    const float* p = &g_part[k * NSLOT * SBIN + bin];
    #pragma unroll
    for (int s = 0; s < NSLOT / 8; s++)
        acc += p[(sub * (NSLOT / 8) + s) * SBIN];
    red[sub][bin] = acc;
    __syncthreads();

    if (sub == 0) {
        float t = 0.f;
        #pragma unroll
        for (int r = 0; r < 8; r++) t += red[r][bin];
        red[0][bin] = t;
    }
    __syncthreads();
    if (sub == 0) {
        float a = 0.f;
        for (int b = 0; b <= bin; b++) a += red[0][b];
        out[k * NBIN + bin] = a;
    }
}

extern "C" void kernel_launch(void* const* d_in, const int* in_sizes, int n_in,
                              void* d_out, int out_size) {
    const float* x    = (const float*)d_in[0];
    const float* dirs = (const float*)d_in[1];
    float* out = (float*)d_out;

    prep_kernel<<<1, 32>>>(dirs, 0);                        // launch 0
    prep_kernel<<<1, 32>>>(dirs, 32);                       // launch 1

    void* src = nullptr;
    cudaGetSymbolAddress(&src, g_dconst);                   // pure query, capture-safe
    cudaMemcpyToSymbolAsync(c_dir, src, sizeof(float4) * NDIR * 3,
                            0, cudaMemcpyDeviceToDevice, 0);

    main_kernel<<<dim3(NTILE, ISEG, NGRP), TPB>>>(x);       // launch 2
    finalize<<<NDIR, 520>>>(out);                           // launch 3
}